// round 10
// baseline (speedup 1.0000x reference)
#include <cuda_runtime.h>
#include <cfloat>
#include <cstdint>

// Problem constants
#define B_   65536
#define I_   640     // input dim (K of encode GEMM)
#define L_   2560    // latent dim
#define K_   32      // top-k

// Encode tiling: block tile 64 rows x 128 cols, 256 threads, 4x8 per thread
#define BM   64
#define BN   128
#define NTHR 256
#define CH   16                 // k per pipeline chunk
#define NC   (I_ / CH)          // 40 chunks

typedef unsigned long long u64;

// ---------------------------------------------------------------------------
// Device-global scratch (no allocation allowed)
// ---------------------------------------------------------------------------
__device__ float g_WdT[(size_t)L_ * I_];   // Wd transposed  [2560][640]
__device__ float g_weT[(size_t)I_ * L_];   // We transposed  [640][2560]
__device__ u64   g_xTd[(size_t)I_ * B_];   // x transposed + dup-packed (a,a)
__device__ float g_topk_v[(size_t)B_ * K_];
__device__ int   g_topk_i[(size_t)B_ * K_];

// ---------------------------------------------------------------------------
// Packed f32x2 helpers (SASS FFMA2)
// ---------------------------------------------------------------------------
__device__ __forceinline__ u64 pack2(float lo, float hi) {
    u64 d; asm("mov.b64 %0, {%1, %2};" : "=l"(d) : "f"(lo), "f"(hi)); return d;
}
__device__ __forceinline__ float2 unpack2(u64 v) {
    float2 r; asm("mov.b64 {%0, %1}, %2;" : "=f"(r.x), "=f"(r.y) : "l"(v));
    return r;
}
__device__ __forceinline__ void ffma2(u64& d, u64 a, u64 b) {
    asm("fma.rn.f32x2 %0, %1, %2, %0;" : "+l"(d) : "l"(a), "l"(b));
}
__device__ __forceinline__ uint32_t smem_u32(const void* p) {
    uint32_t a;
    asm("{ .reg .u64 t; cvta.to.shared.u64 t, %1; cvt.u32.u64 %0, t; }"
        : "=r"(a) : "l"(p));
    return a;
}
#define CP16(dst_u32, src_ptr) \
    asm volatile("cp.async.cg.shared.global [%0], [%1], 16;" \
                 :: "r"(dst_u32), "l"(src_ptr) : "memory")
#define CP_COMMIT()  asm volatile("cp.async.commit_group;" ::: "memory")
#define CP_WAIT0()   asm volatile("cp.async.wait_group 0;" ::: "memory")

// ---------------------------------------------------------------------------
// SMEM layout (byte offsets). Stage s at s*16384: A(8K dup u64) + B(8K f32).
// Cs overlays stage 0 as swizzled [64 rows][16 uint4] (one 64-col half-tile).
// ---------------------------------------------------------------------------
#define SM_STAGE(s) ((s) * 16384)
#define SM_A_OFF    0
#define SM_B_OFF    8192
#define SM_CS       0
#define SM_SV       32768   // f32 [64][33]  8448
#define SM_SI       41216   // i16 [64][33]  4224
#define SM_BE       45440   // f32 [128]      512
#define SM_TOT      45952

// ---------------------------------------------------------------------------
// Kernel: generic 32x32 tiled transpose  dst[c][r] = src[r][c]
// ---------------------------------------------------------------------------
__global__ void transpose_kernel(const float* __restrict__ src,
                                 float* __restrict__ dst,
                                 int rows, int cols) {
    __shared__ float t[32][33];
    const int c0 = blockIdx.x * 32, r0 = blockIdx.y * 32;
    const int tx = threadIdx.x, ty = threadIdx.y;
    #pragma unroll
    for (int r = ty; r < 32; r += 8)
        t[r][tx] = src[(size_t)(r0 + r) * cols + c0 + tx];
    __syncthreads();
    #pragma unroll
    for (int r = ty; r < 32; r += 8)
        dst[(size_t)(c0 + r) * rows + r0 + tx] = t[tx][r];
}

// ---------------------------------------------------------------------------
// Kernel: transpose + dup-pack x:  g_xTd[k][b] = (x[b][k], x[b][k])
// ---------------------------------------------------------------------------
__global__ void transpose_dup_kernel(const float* __restrict__ x) {
    __shared__ float t[32][33];
    const int k0 = blockIdx.x * 32, b0 = blockIdx.y * 32;
    const int tx = threadIdx.x, ty = threadIdx.y;
    #pragma unroll
    for (int r = ty; r < 32; r += 8)
        t[r][tx] = x[(size_t)(b0 + r) * I_ + k0 + tx];
    __syncthreads();
    #pragma unroll
    for (int r = ty; r < 32; r += 8) {
        float v = t[tx][r];
        g_xTd[(size_t)(k0 + r) * B_ + b0 + tx] = pack2(v, v);
    }
}

// ---------------------------------------------------------------------------
// Fragment load/compute macros (stage-relative), 4x8 thread tile
//   A frag: 2 x LDS.128 of dup-packed u64 (broadcast by ty)
//   B frag: 2 x LDS.128, lanes cover 16 consecutive 16B lines (conflict-free)
// ---------------------------------------------------------------------------
#define LDA(base, kk, A)                                                \
    {                                                                   \
        const ulonglong2* p =                                           \
            (const ulonglong2*)((base) + (kk) * 512 + ty * 32);         \
        (A)[0] = p[0]; (A)[1] = p[1];                                   \
    }
#define LDB(base, kk, Bv)                                               \
    {                                                                   \
        const char* q = (base) + SM_B_OFF + (kk) * 512 + tx * 16;       \
        (Bv)[0] = *(const ulonglong2*)(q);                              \
        (Bv)[1] = *(const ulonglong2*)(q + 256);                        \
    }
#define COMP(A, Bv)                                                     \
    {                                                                   \
        _Pragma("unroll")                                               \
        for (int i = 0; i < 2; ++i) {                                   \
            ffma2(acc[2*i][0],   (A)[i].x, (Bv)[0].x);                  \
            ffma2(acc[2*i][1],   (A)[i].x, (Bv)[0].y);                  \
            ffma2(acc[2*i][2],   (A)[i].x, (Bv)[1].x);                  \
            ffma2(acc[2*i][3],   (A)[i].x, (Bv)[1].y);                  \
            ffma2(acc[2*i+1][0], (A)[i].y, (Bv)[0].x);                  \
            ffma2(acc[2*i+1][1], (A)[i].y, (Bv)[0].y);                  \
            ffma2(acc[2*i+1][2], (A)[i].y, (Bv)[1].x);                  \
            ffma2(acc[2*i+1][3], (A)[i].y, (Bv)[1].y);                  \
        }                                                               \
    }

// ---------------------------------------------------------------------------
// Kernel: exact fp32 encode GEMM (FFMA2, cp.async 2-stage, 24 warps/SM) +
//         exact streaming top-32 (float4 swizzled scan) + scatter.
// ---------------------------------------------------------------------------
__global__ void __launch_bounds__(NTHR, 3)
encode_topk_kernel(const float* __restrict__ be,
                   float* __restrict__ sparse_out) {
    extern __shared__ __align__(16) char smem[];
    const uint32_t sb = smem_u32(smem);
    uint4* CsU = (uint4*)(smem + SM_CS);   // swizzled [64][16]
    float* sv  = (float*)(smem + SM_SV);
    short* si  = (short*)(smem + SM_SI);
    float* sbe = (float*)(smem + SM_BE);

    const int tid  = threadIdx.x;
    const int tx   = tid & 15;   // col groups: tx*4 and 64+tx*4
    const int ty   = tid >> 4;   // row group: ty*4 .. ty*4+3   (0..15)
    const int row0 = blockIdx.x * BM;

    // init top-k lists
    for (int i = tid; i < BM * K_; i += NTHR) {
        int r = i >> 5, k = i & 31;
        sv[r * 33 + k] = -FLT_MAX;
        si[r * 33 + k] = 32767;
    }
    __syncthreads();

    // staging issue: chunk c -> stage s (512 x 16B for A, 512 x 16B for B)
    auto issue_chunk = [&](int ct, int c, int s) {
        const int k0   = c * CH;
        const int col0 = ct * BN;
        const uint32_t abase = sb + SM_STAGE(s) + SM_A_OFF;
        const uint32_t bbase = sb + SM_STAGE(s) + SM_B_OFF;
        #pragma unroll
        for (int it = 0; it < 2; ++it) {
            int u = tid + it * NTHR;      // 0..511
            int k = u >> 5, q = u & 31;
            const char* asrc = (const char*)(g_xTd
                + (size_t)(k0 + k) * B_ + row0 + q * 2);
            CP16(abase + k * 512 + q * 16, asrc);
            const char* bsrc = (const char*)(g_weT
                + (size_t)(k0 + k) * L_ + (col0 + q * 4));
            CP16(bbase + k * 512 + q * 16, bsrc);
        }
        CP_COMMIT();
    };

    float minv = -FLT_MAX;
    int   mini = 32767;

    // prefetch tile 0 chunk 0
    issue_chunk(0, 0, 0);
    if (tid < BN) sbe[tid] = be[tid];

    for (int ct = 0; ct < L_ / BN; ++ct) {
        const int col0 = ct * BN;

        u64 acc[4][4];
        #pragma unroll
        for (int i = 0; i < 4; ++i)
            #pragma unroll
            for (int j = 0; j < 4; ++j) acc[i][j] = 0ull;

        for (int c = 0; c < NC; ++c) {
            CP_WAIT0();
            __syncthreads();            // chunk c visible; c-1 consumers done
            if (c + 1 < NC) issue_chunk(ct, c + 1, (c + 1) & 1);

            const char* base = smem + SM_STAGE(c & 1);
            ulonglong2 aC[2], bC[2], aN[2], bN[2];
            LDA(base, 0, aC); LDB(base, 0, bC);
            #pragma unroll
            for (int k = 0; k < CH; k += 2) {
                LDA(base, k + 1, aN); LDB(base, k + 1, bN);
                COMP(aC, bC);
                if (k + 2 < CH) { LDA(base, k + 2, aC); LDB(base, k + 2, bC); }
                COMP(aN, bN);
            }
            __syncthreads();            // chunk c consumed before overwrite
        }

        // two 64-col halves: epilogue (swizzled Cs over stage 0) + scan
        #pragma unroll
        for (int h = 0; h < 2; ++h) {
            // epilogue: bias + swizzled store, one float4 per row
            #pragma unroll
            for (int i = 0; i < 4; ++i) {
                const int r = ty * 4 + i;
                float2 p0 = unpack2(acc[i][2 * h]);
                float2 p1 = unpack2(acc[i][2 * h + 1]);
                const int n0 = h * 64 + tx * 4;
                float4 f = make_float4(p0.x + sbe[n0],     p0.y + sbe[n0 + 1],
                                       p1.x + sbe[n0 + 2], p1.y + sbe[n0 + 3]);
                CsU[r * 16 + ((tx + r) & 15)] = *(uint4*)&f;
            }
            __syncthreads();

            // scan: thread t owns row t, 16 swizzled float4 reads
            if (tid < BM) {
                const int lbase = tid * 33;
                #pragma unroll 1
                for (int c4 = 0; c4 < 16; ++c4) {
                    uint4 u = CsU[tid * 16 + ((c4 + tid) & 15)];
                    float4 v = *(float4*)&u;
                    float vmax = fmaxf(fmaxf(v.x, v.y), fmaxf(v.z, v.w));
                    if (vmax < minv) continue;   // exact: ties have v==minv
                    const float vs[4] = {v.x, v.y, v.z, v.w};
                    #pragma unroll 1
                    for (int e = 0; e < 4; ++e) {
                        float val = vs[e];
                        int col = col0 + h * 64 + c4 * 4 + e;
                        if (val > minv || (val == minv && col < mini)) {
                            int p = K_ - 1;
                            while (p > 0) {
                                float pv = sv[lbase + p - 1];
                                int   pi = si[lbase + p - 1];
                                if (val > pv || (val == pv && col < pi)) {
                                    sv[lbase + p] = pv;
                                    si[lbase + p] = (short)pi; --p;
                                } else break;
                            }
                            sv[lbase + p] = val; si[lbase + p] = (short)col;
                            minv = sv[lbase + K_ - 1];
                            mini = si[lbase + K_ - 1];
                        }
                    }
                }
            }
            __syncthreads();
        }

        // prefetch next tile's chunk 0 (stage 0 free again) + next bias
        if (ct + 1 < L_ / BN) {
            issue_chunk(ct + 1, 0, 0);
            if (tid < BN) sbe[tid] = be[col0 + BN + tid];
        }
    }

    // publish topk for decode
    if (tid < BM) {
        const size_t brow = (size_t)(row0 + tid);
        #pragma unroll
        for (int k = 0; k < K_; ++k) {
            g_topk_v[brow * K_ + k] = sv[tid * 33 + k];
            g_topk_i[brow * K_ + k] = (int)si[tid * 33 + k];
        }
    }

    // zero-fill this block's sparse region, then scatter winners
    {
        float4 z = make_float4(0.f, 0.f, 0.f, 0.f);
        float4* sp = (float4*)(sparse_out + (size_t)row0 * L_);
        for (int i = tid; i < BM * L_ / 4; i += NTHR) sp[i] = z;
    }
    __syncthreads();
    if (tid < BM) {
        const size_t brow = (size_t)(row0 + tid);
        #pragma unroll
        for (int k = 0; k < K_; ++k)
            sparse_out[brow * L_ + (int)si[tid * 33 + k]] = sv[tid * 33 + k];
    }
}

// ---------------------------------------------------------------------------
// Kernel: sparse decode.  recon[b,i] = bd[i] + sum_k v_k * WdT[idx_k, i]
// ---------------------------------------------------------------------------
__global__ void __launch_bounds__(128)
decode_kernel(const float* __restrict__ bd, float* __restrict__ recon) {
    __shared__ float sv[K_];
    __shared__ int   si[K_];
    const int b = blockIdx.x, t = threadIdx.x;
    if (t < K_) {
        sv[t] = g_topk_v[(size_t)b * K_ + t];
        si[t] = g_topk_i[(size_t)b * K_ + t];
    }
    __syncthreads();

    float acc[5];
    #pragma unroll
    for (int j = 0; j < 5; ++j) acc[j] = __ldg(&bd[t + j * 128]);
    #pragma unroll 1
    for (int k = 0; k < K_; ++k) {
        float v = sv[k];
        const float* cw = g_WdT + (size_t)si[k] * I_;
        #pragma unroll
        for (int j = 0; j < 5; ++j)
            acc[j] = fmaf(v, __ldg(&cw[t + j * 128]), acc[j]);
    }
    #pragma unroll
    for (int j = 0; j < 5; ++j)
        recon[(size_t)b * I_ + t + j * 128] = acc[j];
}

// ---------------------------------------------------------------------------
// Launch
// ---------------------------------------------------------------------------
extern "C" void kernel_launch(void* const* d_in, const int* in_sizes, int n_in,
                              void* d_out, int out_size) {
    const float* x  = (const float*)d_in[0];   // [65536, 640]
    const float* We = (const float*)d_in[1];   // [2560, 640]
    const float* be = (const float*)d_in[2];   // [2560]
    const float* Wd = (const float*)d_in[3];   // [640, 2560]
    const float* bd = (const float*)d_in[4];   // [640]

    float* recon  = (float*)d_out;                    // [B_, I_]
    float* sparse = (float*)d_out + (size_t)B_ * I_;  // [B_, L_]

    float *wdt, *wet;
    cudaGetSymbolAddress((void**)&wdt, g_WdT);
    cudaGetSymbolAddress((void**)&wet, g_weT);

    cudaFuncSetAttribute(encode_topk_kernel,
                         cudaFuncAttributeMaxDynamicSharedMemorySize, SM_TOT);

    transpose_kernel<<<dim3(L_ / 32, I_ / 32), dim3(32, 8)>>>(Wd, wdt, I_, L_);
    transpose_kernel<<<dim3(I_ / 32, L_ / 32), dim3(32, 8)>>>(We, wet, L_, I_);
    transpose_dup_kernel<<<dim3(I_ / 32, B_ / 32), dim3(32, 8)>>>(x);

    encode_topk_kernel<<<B_ / BM, NTHR, SM_TOT>>>(be, sparse);
    decode_kernel<<<B_, 128>>>(bd, recon);
}

// round 11
// speedup vs baseline: 1.3308x; 1.3308x over previous
#include <cuda_runtime.h>
#include <cfloat>
#include <cstdint>

// Problem constants
#define B_   65536
#define I_   640     // input dim (K of encode GEMM)
#define L_   2560    // latent dim
#define K_   32      // top-k

// Encode tiling: block tile 64 rows x 128 cols, 128 threads, 8x8 per thread
#define BM   64
#define BN   128
#define NTHR 128
#define CH   16                 // k per pipeline chunk
#define NC   (I_ / CH)          // 40 chunks

typedef unsigned long long u64;

// ---------------------------------------------------------------------------
// Device-global scratch (no allocation allowed)
// ---------------------------------------------------------------------------
__device__ float g_WdT[(size_t)L_ * I_];   // Wd transposed  [2560][640]
__device__ float g_weT[(size_t)I_ * L_];   // We transposed  [640][2560]
__device__ u64   g_xTd[(size_t)I_ * B_];   // x transposed + dup-packed (a,a)
__device__ float g_topk_v[(size_t)B_ * K_];
__device__ int   g_topk_i[(size_t)B_ * K_];

// ---------------------------------------------------------------------------
// Packed f32x2 helpers (SASS FFMA2)
// ---------------------------------------------------------------------------
__device__ __forceinline__ u64 pack2(float lo, float hi) {
    u64 d; asm("mov.b64 %0, {%1, %2};" : "=l"(d) : "f"(lo), "f"(hi)); return d;
}
__device__ __forceinline__ float2 unpack2(u64 v) {
    float2 r; asm("mov.b64 {%0, %1}, %2;" : "=f"(r.x), "=f"(r.y) : "l"(v));
    return r;
}
__device__ __forceinline__ void ffma2(u64& d, u64 a, u64 b) {
    asm("fma.rn.f32x2 %0, %1, %2, %0;" : "+l"(d) : "l"(a), "l"(b));
}
__device__ __forceinline__ uint32_t smem_u32(const void* p) {
    uint32_t a;
    asm("{ .reg .u64 t; cvta.to.shared.u64 t, %1; cvt.u32.u64 %0, t; }"
        : "=r"(a) : "l"(p));
    return a;
}
#define CP16(dst_u32, src_ptr) \
    asm volatile("cp.async.cg.shared.global [%0], [%1], 16;" \
                 :: "r"(dst_u32), "l"(src_ptr) : "memory")
#define CP_COMMIT()  asm volatile("cp.async.commit_group;" ::: "memory")
#define CP_WAIT0()   asm volatile("cp.async.wait_group 0;" ::: "memory")

// ---------------------------------------------------------------------------
// SMEM layout (byte offsets). Stage s at s*16384: A(8K dup u64) + B(8K f32).
// Cs overlays stage 0 as swizzled [64 rows][16 uint4] (one 64-col half-tile).
// ---------------------------------------------------------------------------
#define SM_STAGE(s) ((s) * 16384)
#define SM_A_OFF    0
#define SM_B_OFF    8192
#define SM_CS       0
#define SM_SV       32768   // f32 [64][33]  8448
#define SM_SI       41216   // i16 [64][33]  4224
#define SM_BE       45440   // f32 [128]      512
#define SM_TOT      45952   // x5 CTAs = 229760 <= 233472 (228KB)

// ---------------------------------------------------------------------------
// Kernel: generic 32x32 tiled transpose  dst[c][r] = src[r][c]
// ---------------------------------------------------------------------------
__global__ void transpose_kernel(const float* __restrict__ src,
                                 float* __restrict__ dst,
                                 int rows, int cols) {
    __shared__ float t[32][33];
    const int c0 = blockIdx.x * 32, r0 = blockIdx.y * 32;
    const int tx = threadIdx.x, ty = threadIdx.y;
    #pragma unroll
    for (int r = ty; r < 32; r += 8)
        t[r][tx] = src[(size_t)(r0 + r) * cols + c0 + tx];
    __syncthreads();
    #pragma unroll
    for (int r = ty; r < 32; r += 8)
        dst[(size_t)(c0 + r) * rows + r0 + tx] = t[tx][r];
}

// ---------------------------------------------------------------------------
// Kernel: transpose + dup-pack x:  g_xTd[k][b] = (x[b][k], x[b][k])
// ---------------------------------------------------------------------------
__global__ void transpose_dup_kernel(const float* __restrict__ x) {
    __shared__ float t[32][33];
    const int k0 = blockIdx.x * 32, b0 = blockIdx.y * 32;
    const int tx = threadIdx.x, ty = threadIdx.y;
    #pragma unroll
    for (int r = ty; r < 32; r += 8)
        t[r][tx] = x[(size_t)(b0 + r) * I_ + k0 + tx];
    __syncthreads();
    #pragma unroll
    for (int r = ty; r < 32; r += 8) {
        float v = t[tx][r];
        g_xTd[(size_t)(k0 + r) * B_ + b0 + tx] = pack2(v, v);
    }
}

// ---------------------------------------------------------------------------
// Fragment load/compute macros (stage-relative), 8x8 thread tile
// ---------------------------------------------------------------------------
#define LDA(base, kk, A)                                                \
    {                                                                   \
        const ulonglong2* p =                                           \
            (const ulonglong2*)((base) + (kk) * 512 + ty * 64);         \
        (A)[0] = p[0]; (A)[1] = p[1]; (A)[2] = p[2]; (A)[3] = p[3];     \
    }
#define LDB(base, kk, Bv)                                               \
    {                                                                   \
        const char* q = (base) + SM_B_OFF + (kk) * 512 + tx * 16;       \
        (Bv)[0] = *(const ulonglong2*)(q);                              \
        (Bv)[1] = *(const ulonglong2*)(q + 256);                        \
    }
#define COMP(A, Bv)                                                     \
    {                                                                   \
        _Pragma("unroll")                                               \
        for (int i = 0; i < 4; ++i) {                                   \
            ffma2(acc[2*i][0],   (A)[i].x, (Bv)[0].x);                  \
            ffma2(acc[2*i][1],   (A)[i].x, (Bv)[0].y);                  \
            ffma2(acc[2*i][2],   (A)[i].x, (Bv)[1].x);                  \
            ffma2(acc[2*i][3],   (A)[i].x, (Bv)[1].y);                  \
            ffma2(acc[2*i+1][0], (A)[i].y, (Bv)[0].x);                  \
            ffma2(acc[2*i+1][1], (A)[i].y, (Bv)[0].y);                  \
            ffma2(acc[2*i+1][2], (A)[i].y, (Bv)[1].x);                  \
            ffma2(acc[2*i+1][3], (A)[i].y, (Bv)[1].y);                  \
        }                                                               \
    }

// ---------------------------------------------------------------------------
// Kernel: exact fp32 encode GEMM (FFMA2, cp.async 2-stage, 5 CTAs/SM) +
//         exact streaming top-32 (float4 swizzled scan) + scatter.
// ---------------------------------------------------------------------------
__global__ void __launch_bounds__(NTHR, 5)
encode_topk_kernel(const float* __restrict__ be,
                   float* __restrict__ sparse_out) {
    extern __shared__ __align__(16) char smem[];
    const uint32_t sb = smem_u32(smem);
    uint4* CsU = (uint4*)(smem + SM_CS);   // swizzled [64][16]
    float* sv  = (float*)(smem + SM_SV);
    short* si  = (short*)(smem + SM_SI);
    float* sbe = (float*)(smem + SM_BE);

    const int tid  = threadIdx.x;
    const int tx   = tid & 15;   // col groups: tx*4 and 64+tx*4
    const int ty   = tid >> 4;   // row group: ty*8 .. ty*8+7
    const int row0 = blockIdx.x * BM;

    // init top-k lists
    for (int i = tid; i < BM * K_; i += NTHR) {
        int r = i >> 5, k = i & 31;
        sv[r * 33 + k] = -FLT_MAX;
        si[r * 33 + k] = 32767;
    }
    __syncthreads();

    // staging issue: chunk c -> stage s (512 x 16B for A, 512 x 16B for B)
    auto issue_chunk = [&](int ct, int c, int s) {
        const int k0   = c * CH;
        const int col0 = ct * BN;
        const uint32_t abase = sb + SM_STAGE(s) + SM_A_OFF;
        const uint32_t bbase = sb + SM_STAGE(s) + SM_B_OFF;
        #pragma unroll
        for (int it = 0; it < 4; ++it) {
            int u = tid + it * NTHR;      // 0..511
            int k = u >> 5, q = u & 31;
            const char* asrc = (const char*)(g_xTd
                + (size_t)(k0 + k) * B_ + row0 + q * 2);
            CP16(abase + k * 512 + q * 16, asrc);
            const char* bsrc = (const char*)(g_weT
                + (size_t)(k0 + k) * L_ + (col0 + q * 4));
            CP16(bbase + k * 512 + q * 16, bsrc);
        }
        CP_COMMIT();
    };

    float minv = -FLT_MAX;
    int   mini = 32767;

    // prefetch tile 0 chunk 0
    issue_chunk(0, 0, 0);
    if (tid < BN) sbe[tid] = be[tid];

    for (int ct = 0; ct < L_ / BN; ++ct) {
        const int col0 = ct * BN;

        u64 acc[8][4];
        #pragma unroll
        for (int i = 0; i < 8; ++i)
            #pragma unroll
            for (int j = 0; j < 4; ++j) acc[i][j] = 0ull;

        for (int c = 0; c < NC; ++c) {
            CP_WAIT0();
            __syncthreads();            // chunk c visible; c-1 consumers done
            if (c + 1 < NC) issue_chunk(ct, c + 1, (c + 1) & 1);

            const char* base = smem + SM_STAGE(c & 1);
            // single-buffered frags: all k-iterations independent; full
            // unroll lets ptxas software-pipeline within the reg budget
            #pragma unroll
            for (int k = 0; k < CH; ++k) {
                ulonglong2 aC[4], bC[2];
                LDA(base, k, aC); LDB(base, k, bC);
                COMP(aC, bC);
            }
            __syncthreads();            // chunk c consumed before overwrite
        }

        // two 64-col halves: epilogue (swizzled Cs over stage 0) + scan
        #pragma unroll
        for (int h = 0; h < 2; ++h) {
            // epilogue: bias + swizzled store, one float4 per row
            #pragma unroll
            for (int i = 0; i < 8; ++i) {
                const int r = ty * 8 + i;
                float2 p0 = unpack2(acc[i][2 * h]);
                float2 p1 = unpack2(acc[i][2 * h + 1]);
                const int n0 = h * 64 + tx * 4;
                float4 f = make_float4(p0.x + sbe[n0],     p0.y + sbe[n0 + 1],
                                       p1.x + sbe[n0 + 2], p1.y + sbe[n0 + 3]);
                CsU[r * 16 + ((tx + r) & 15)] = *(uint4*)&f;
            }
            __syncthreads();

            // scan: thread t owns row t, 16 swizzled float4 reads
            if (tid < BM) {
                const int lbase = tid * 33;
                #pragma unroll 1
                for (int c4 = 0; c4 < 16; ++c4) {
                    uint4 u = CsU[tid * 16 + ((c4 + tid) & 15)];
                    float4 v = *(float4*)&u;
                    float vmax = fmaxf(fmaxf(v.x, v.y), fmaxf(v.z, v.w));
                    if (vmax < minv) continue;   // exact: ties have v==minv
                    const float vs[4] = {v.x, v.y, v.z, v.w};
                    #pragma unroll 1
                    for (int e = 0; e < 4; ++e) {
                        float val = vs[e];
                        int col = col0 + h * 64 + c4 * 4 + e;
                        if (val > minv || (val == minv && col < mini)) {
                            int p = K_ - 1;
                            while (p > 0) {
                                float pv = sv[lbase + p - 1];
                                int   pi = si[lbase + p - 1];
                                if (val > pv || (val == pv && col < pi)) {
                                    sv[lbase + p] = pv;
                                    si[lbase + p] = (short)pi; --p;
                                } else break;
                            }
                            sv[lbase + p] = val; si[lbase + p] = (short)col;
                            minv = sv[lbase + K_ - 1];
                            mini = si[lbase + K_ - 1];
                        }
                    }
                }
            }
            __syncthreads();
        }

        // prefetch next tile's chunk 0 (stage 0 free again) + next bias
        if (ct + 1 < L_ / BN) {
            issue_chunk(ct + 1, 0, 0);
            if (tid < BN) sbe[tid] = be[col0 + BN + tid];
        }
    }

    // publish topk for decode
    if (tid < BM) {
        const size_t brow = (size_t)(row0 + tid);
        #pragma unroll
        for (int k = 0; k < K_; ++k) {
            g_topk_v[brow * K_ + k] = sv[tid * 33 + k];
            g_topk_i[brow * K_ + k] = (int)si[tid * 33 + k];
        }
    }

    // zero-fill this block's sparse region, then scatter winners
    {
        float4 z = make_float4(0.f, 0.f, 0.f, 0.f);
        float4* sp = (float4*)(sparse_out + (size_t)row0 * L_);
        for (int i = tid; i < BM * L_ / 4; i += NTHR) sp[i] = z;
    }
    __syncthreads();
    if (tid < BM) {
        const size_t brow = (size_t)(row0 + tid);
        #pragma unroll
        for (int k = 0; k < K_; ++k)
            sparse_out[brow * L_ + (int)si[tid * 33 + k]] = sv[tid * 33 + k];
    }
}

// ---------------------------------------------------------------------------
// Kernel: sparse decode.  recon[b,i] = bd[i] + sum_k v_k * WdT[idx_k, i]
// ---------------------------------------------------------------------------
__global__ void __launch_bounds__(128)
decode_kernel(const float* __restrict__ bd, float* __restrict__ recon) {
    __shared__ float sv[K_];
    __shared__ int   si[K_];
    const int b = blockIdx.x, t = threadIdx.x;
    if (t < K_) {
        sv[t] = g_topk_v[(size_t)b * K_ + t];
        si[t] = g_topk_i[(size_t)b * K_ + t];
    }
    __syncthreads();

    float acc[5];
    #pragma unroll
    for (int j = 0; j < 5; ++j) acc[j] = __ldg(&bd[t + j * 128]);
    #pragma unroll 1
    for (int k = 0; k < K_; ++k) {
        float v = sv[k];
        const float* cw = g_WdT + (size_t)si[k] * I_;
        #pragma unroll
        for (int j = 0; j < 5; ++j)
            acc[j] = fmaf(v, __ldg(&cw[t + j * 128]), acc[j]);
    }
    #pragma unroll
    for (int j = 0; j < 5; ++j)
        recon[(size_t)b * I_ + t + j * 128] = acc[j];
}

// ---------------------------------------------------------------------------
// Launch
// ---------------------------------------------------------------------------
extern "C" void kernel_launch(void* const* d_in, const int* in_sizes, int n_in,
                              void* d_out, int out_size) {
    const float* x  = (const float*)d_in[0];   // [65536, 640]
    const float* We = (const float*)d_in[1];   // [2560, 640]
    const float* be = (const float*)d_in[2];   // [2560]
    const float* Wd = (const float*)d_in[3];   // [640, 2560]
    const float* bd = (const float*)d_in[4];   // [640]

    float* recon  = (float*)d_out;                    // [B_, I_]
    float* sparse = (float*)d_out + (size_t)B_ * I_;  // [B_, L_]

    float *wdt, *wet;
    cudaGetSymbolAddress((void**)&wdt, g_WdT);
    cudaGetSymbolAddress((void**)&wet, g_weT);

    cudaFuncSetAttribute(encode_topk_kernel,
                         cudaFuncAttributeMaxDynamicSharedMemorySize, SM_TOT);

    transpose_kernel<<<dim3(L_ / 32, I_ / 32), dim3(32, 8)>>>(Wd, wdt, I_, L_);
    transpose_kernel<<<dim3(I_ / 32, L_ / 32), dim3(32, 8)>>>(We, wet, L_, I_);
    transpose_dup_kernel<<<dim3(I_ / 32, B_ / 32), dim3(32, 8)>>>(x);

    encode_topk_kernel<<<B_ / BM, NTHR, SM_TOT>>>(be, sparse);
    decode_kernel<<<B_, 128>>>(bd, recon);
}

// round 12
// speedup vs baseline: 1.5240x; 1.1451x over previous
#include <cuda_runtime.h>
#include <cfloat>
#include <cstdint>

// Problem constants
#define B_   65536
#define I_   640     // input dim (K of encode GEMM)
#define L_   2560    // latent dim
#define K_   32      // top-k

// Encode tiling: block tile 64 rows x 128 cols, 128 threads, 8x8 per thread
#define BM   64
#define BN   128
#define NTHR 128
#define CH   16                 // k per pipeline chunk
#define NC   (I_ / CH)          // 40 chunks

typedef unsigned long long u64;

// ---------------------------------------------------------------------------
// Device-global scratch (no allocation allowed)
// ---------------------------------------------------------------------------
__device__ float g_WdT[(size_t)L_ * I_];   // Wd transposed  [2560][640]
__device__ float g_weT[(size_t)I_ * L_];   // We transposed  [640][2560]
__device__ float g_xT [(size_t)I_ * B_];   // x  transposed  [640][65536]
__device__ float g_topk_v[(size_t)B_ * K_];
__device__ int   g_topk_i[(size_t)B_ * K_];

// ---------------------------------------------------------------------------
// Packed f32x2 helpers (SASS FFMA2)
// ---------------------------------------------------------------------------
__device__ __forceinline__ u64 pack2(float lo, float hi) {
    u64 d; asm("mov.b64 %0, {%1, %2};" : "=l"(d) : "f"(lo), "f"(hi)); return d;
}
__device__ __forceinline__ float2 unpack2(u64 v) {
    float2 r; asm("mov.b64 {%0, %1}, %2;" : "=f"(r.x), "=f"(r.y) : "l"(v));
    return r;
}
__device__ __forceinline__ void ffma2(u64& d, u64 a, u64 b) {
    asm("fma.rn.f32x2 %0, %1, %2, %0;" : "+l"(d) : "l"(a), "l"(b));
}
__device__ __forceinline__ uint32_t smem_u32(const void* p) {
    uint32_t a;
    asm("{ .reg .u64 t; cvta.to.shared.u64 t, %1; cvt.u32.u64 %0, t; }"
        : "=r"(a) : "l"(p));
    return a;
}
#define CP16(dst_u32, src_ptr) \
    asm volatile("cp.async.cg.shared.global [%0], [%1], 16;" \
                 :: "r"(dst_u32), "l"(src_ptr) : "memory")
#define CP_COMMIT()  asm volatile("cp.async.commit_group;" ::: "memory")
#define CP_WAIT0()   asm volatile("cp.async.wait_group 0;" ::: "memory")

// ---------------------------------------------------------------------------
// SMEM layout (byte offsets). Stage s = 12288 B: A plain f32 [16][64] (4 KB)
// + B f32 [16][128] (8 KB).  Cs (16 KB) overlays stage0 + part of stage1
// (both dead during epilogue/scan).
// ---------------------------------------------------------------------------
#define SM_STG      12288
#define SM_STAGE(s) ((s) * SM_STG)
#define SM_A_OFF    0
#define SM_B_OFF    4096
#define SM_CS       0
#define SM_SV       24576   // f32 [64][33]  8448
#define SM_SI       33024   // i16 [64][33]  4224
#define SM_BE       37248   // f32 [128]      512
#define SM_TOT      37760

// ---------------------------------------------------------------------------
// Kernel: generic 32x32 tiled transpose  dst[c][r] = src[r][c]
// ---------------------------------------------------------------------------
__global__ void transpose_kernel(const float* __restrict__ src,
                                 float* __restrict__ dst,
                                 int rows, int cols) {
    __shared__ float t[32][33];
    const int c0 = blockIdx.x * 32, r0 = blockIdx.y * 32;
    const int tx = threadIdx.x, ty = threadIdx.y;
    #pragma unroll
    for (int r = ty; r < 32; r += 8)
        t[r][tx] = src[(size_t)(r0 + r) * cols + c0 + tx];
    __syncthreads();
    #pragma unroll
    for (int r = ty; r < 32; r += 8)
        dst[(size_t)(c0 + r) * rows + r0 + tx] = t[tx][r];
}

// ---------------------------------------------------------------------------
// Fragment load/compute macros (stage-relative), 8x8 thread tile
//   A: 2 x LDS.128 of plain f32 (8 consecutive rows), dup-packed via 8 movs
//      (movs issue on the alu pipe — off the FFMA2/LDS critical pipes)
//   B: 2 x LDS.128, lanes cover 16 consecutive 16B lines (conflict-free)
// ---------------------------------------------------------------------------
#define LDA(base, kk, AD)                                               \
    {                                                                   \
        const float4* p =                                               \
            (const float4*)((base) + (kk) * 256 + ty * 32);             \
        float4 f0 = p[0], f1 = p[1];                                    \
        (AD)[0] = pack2(f0.x, f0.x); (AD)[1] = pack2(f0.y, f0.y);       \
        (AD)[2] = pack2(f0.z, f0.z); (AD)[3] = pack2(f0.w, f0.w);       \
        (AD)[4] = pack2(f1.x, f1.x); (AD)[5] = pack2(f1.y, f1.y);       \
        (AD)[6] = pack2(f1.z, f1.z); (AD)[7] = pack2(f1.w, f1.w);       \
    }
#define LDB(base, kk, Bv)                                               \
    {                                                                   \
        const char* q = (base) + SM_B_OFF + (kk) * 512 + tx * 16;       \
        (Bv)[0] = *(const ulonglong2*)(q);                              \
        (Bv)[1] = *(const ulonglong2*)(q + 256);                        \
    }
#define COMP(AD, Bv)                                                    \
    {                                                                   \
        _Pragma("unroll")                                               \
        for (int i = 0; i < 8; ++i) {                                   \
            ffma2(acc[i][0], (AD)[i], (Bv)[0].x);                       \
            ffma2(acc[i][1], (AD)[i], (Bv)[0].y);                       \
            ffma2(acc[i][2], (AD)[i], (Bv)[1].x);                       \
            ffma2(acc[i][3], (AD)[i], (Bv)[1].y);                       \
        }                                                               \
    }

// ---------------------------------------------------------------------------
// Kernel: exact fp32 encode GEMM (FFMA2, cp.async 2-stage) +
//         exact streaming top-32 (float4 swizzled scan) + scatter.
// ---------------------------------------------------------------------------
__global__ void __launch_bounds__(NTHR, 4)
encode_topk_kernel(const float* __restrict__ be,
                   float* __restrict__ sparse_out) {
    extern __shared__ __align__(16) char smem[];
    const uint32_t sb = smem_u32(smem);
    uint4* CsU = (uint4*)(smem + SM_CS);   // swizzled [64][16]
    float* sv  = (float*)(smem + SM_SV);
    short* si  = (short*)(smem + SM_SI);
    float* sbe = (float*)(smem + SM_BE);

    const int tid  = threadIdx.x;
    const int tx   = tid & 15;   // col groups: tx*4 and 64+tx*4
    const int ty   = tid >> 4;   // row group: ty*8 .. ty*8+7
    const int row0 = blockIdx.x * BM;

    // init top-k lists
    for (int i = tid; i < BM * K_; i += NTHR) {
        int r = i >> 5, k = i & 31;
        sv[r * 33 + k] = -FLT_MAX;
        si[r * 33 + k] = 32767;
    }
    __syncthreads();

    // staging issue: chunk c -> stage s (A: 256 x 16B, B: 512 x 16B)
    auto issue_chunk = [&](int ct, int c, int s) {
        const int k0   = c * CH;
        const int col0 = ct * BN;
        const uint32_t abase = sb + SM_STAGE(s) + SM_A_OFF;
        const uint32_t bbase = sb + SM_STAGE(s) + SM_B_OFF;
        #pragma unroll
        for (int it = 0; it < 2; ++it) {
            int u = tid + it * NTHR;      // 0..255
            int k = u >> 4, q = u & 15;
            const char* asrc = (const char*)(g_xT
                + (size_t)(k0 + k) * B_ + row0 + q * 4);
            CP16(abase + k * 256 + q * 16, asrc);
        }
        #pragma unroll
        for (int it = 0; it < 4; ++it) {
            int u = tid + it * NTHR;      // 0..511
            int k = u >> 5, q = u & 31;
            const char* bsrc = (const char*)(g_weT
                + (size_t)(k0 + k) * L_ + (col0 + q * 4));
            CP16(bbase + k * 512 + q * 16, bsrc);
        }
        CP_COMMIT();
    };

    float minv = -FLT_MAX;
    int   mini = 32767;

    // prefetch tile 0 chunk 0
    issue_chunk(0, 0, 0);
    if (tid < BN) sbe[tid] = be[tid];

    for (int ct = 0; ct < L_ / BN; ++ct) {
        const int col0 = ct * BN;

        u64 acc[8][4];
        #pragma unroll
        for (int i = 0; i < 8; ++i)
            #pragma unroll
            for (int j = 0; j < 4; ++j) acc[i][j] = 0ull;

        for (int c = 0; c < NC; ++c) {
            CP_WAIT0();
            __syncthreads();            // chunk c visible; c-1 consumers done
            if (c + 1 < NC) issue_chunk(ct, c + 1, (c + 1) & 1);

            const char* base = smem + SM_STAGE(c & 1);
            #pragma unroll
            for (int k = 0; k < CH; ++k) {
                u64        AD[8];
                ulonglong2 Bv[2];
                LDA(base, k, AD); LDB(base, k, Bv);
                COMP(AD, Bv);
            }
            __syncthreads();            // chunk c consumed before overwrite
        }

        // two 64-col halves: epilogue (swizzled Cs over stages) + scan
        #pragma unroll
        for (int h = 0; h < 2; ++h) {
            // epilogue: bias + swizzled store, one float4 per row
            #pragma unroll
            for (int i = 0; i < 8; ++i) {
                const int r = ty * 8 + i;
                float2 p0 = unpack2(acc[i][2 * h]);
                float2 p1 = unpack2(acc[i][2 * h + 1]);
                const int n0 = h * 64 + tx * 4;
                float4 f = make_float4(p0.x + sbe[n0],     p0.y + sbe[n0 + 1],
                                       p1.x + sbe[n0 + 2], p1.y + sbe[n0 + 3]);
                CsU[r * 16 + ((tx + r) & 15)] = *(uint4*)&f;
            }
            __syncthreads();

            // scan: thread t owns row t, 16 swizzled float4 reads
            if (tid < BM) {
                const int lbase = tid * 33;
                #pragma unroll 1
                for (int c4 = 0; c4 < 16; ++c4) {
                    uint4 u = CsU[tid * 16 + ((c4 + tid) & 15)];
                    float4 v = *(float4*)&u;
                    float vmax = fmaxf(fmaxf(v.x, v.y), fmaxf(v.z, v.w));
                    if (vmax < minv) continue;   // exact: ties have v==minv
                    const float vs[4] = {v.x, v.y, v.z, v.w};
                    #pragma unroll 1
                    for (int e = 0; e < 4; ++e) {
                        float val = vs[e];
                        int col = col0 + h * 64 + c4 * 4 + e;
                        if (val > minv || (val == minv && col < mini)) {
                            int p = K_ - 1;
                            while (p > 0) {
                                float pv = sv[lbase + p - 1];
                                int   pi = si[lbase + p - 1];
                                if (val > pv || (val == pv && col < pi)) {
                                    sv[lbase + p] = pv;
                                    si[lbase + p] = (short)pi; --p;
                                } else break;
                            }
                            sv[lbase + p] = val; si[lbase + p] = (short)col;
                            minv = sv[lbase + K_ - 1];
                            mini = si[lbase + K_ - 1];
                        }
                    }
                }
            }
            __syncthreads();
        }

        // prefetch next tile's chunk 0 (stages free again) + next bias
        if (ct + 1 < L_ / BN) {
            issue_chunk(ct + 1, 0, 0);
            if (tid < BN) sbe[tid] = be[col0 + BN + tid];
        }
    }

    // publish topk for decode
    if (tid < BM) {
        const size_t brow = (size_t)(row0 + tid);
        #pragma unroll
        for (int k = 0; k < K_; ++k) {
            g_topk_v[brow * K_ + k] = sv[tid * 33 + k];
            g_topk_i[brow * K_ + k] = (int)si[tid * 33 + k];
        }
    }

    // zero-fill this block's sparse region, then scatter winners
    {
        float4 z = make_float4(0.f, 0.f, 0.f, 0.f);
        float4* sp = (float4*)(sparse_out + (size_t)row0 * L_);
        for (int i = tid; i < BM * L_ / 4; i += NTHR) sp[i] = z;
    }
    __syncthreads();
    if (tid < BM) {
        const size_t brow = (size_t)(row0 + tid);
        #pragma unroll
        for (int k = 0; k < K_; ++k)
            sparse_out[brow * L_ + (int)si[tid * 33 + k]] = sv[tid * 33 + k];
    }
}

// ---------------------------------------------------------------------------
// Kernel: sparse decode.  recon[b,i] = bd[i] + sum_k v_k * WdT[idx_k, i]
// ---------------------------------------------------------------------------
__global__ void __launch_bounds__(128)
decode_kernel(const float* __restrict__ bd, float* __restrict__ recon) {
    __shared__ float sv[K_];
    __shared__ int   si[K_];
    const int b = blockIdx.x, t = threadIdx.x;
    if (t < K_) {
        sv[t] = g_topk_v[(size_t)b * K_ + t];
        si[t] = g_topk_i[(size_t)b * K_ + t];
    }
    __syncthreads();

    float acc[5];
    #pragma unroll
    for (int j = 0; j < 5; ++j) acc[j] = __ldg(&bd[t + j * 128]);
    #pragma unroll 1
    for (int k = 0; k < K_; ++k) {
        float v = sv[k];
        const float* cw = g_WdT + (size_t)si[k] * I_;
        #pragma unroll
        for (int j = 0; j < 5; ++j)
            acc[j] = fmaf(v, __ldg(&cw[t + j * 128]), acc[j]);
    }
    #pragma unroll
    for (int j = 0; j < 5; ++j)
        recon[(size_t)b * I_ + t + j * 128] = acc[j];
}

// ---------------------------------------------------------------------------
// Launch
// ---------------------------------------------------------------------------
extern "C" void kernel_launch(void* const* d_in, const int* in_sizes, int n_in,
                              void* d_out, int out_size) {
    const float* x  = (const float*)d_in[0];   // [65536, 640]
    const float* We = (const float*)d_in[1];   // [2560, 640]
    const float* be = (const float*)d_in[2];   // [2560]
    const float* Wd = (const float*)d_in[3];   // [640, 2560]
    const float* bd = (const float*)d_in[4];   // [640]

    float* recon  = (float*)d_out;                    // [B_, I_]
    float* sparse = (float*)d_out + (size_t)B_ * I_;  // [B_, L_]

    float *wdt, *wet, *xt;
    cudaGetSymbolAddress((void**)&wdt, g_WdT);
    cudaGetSymbolAddress((void**)&wet, g_weT);
    cudaGetSymbolAddress((void**)&xt,  g_xT);

    cudaFuncSetAttribute(encode_topk_kernel,
                         cudaFuncAttributeMaxDynamicSharedMemorySize, SM_TOT);

    transpose_kernel<<<dim3(L_ / 32, I_ / 32), dim3(32, 8)>>>(Wd, wdt, I_, L_);
    transpose_kernel<<<dim3(I_ / 32, L_ / 32), dim3(32, 8)>>>(We, wet, L_, I_);
    transpose_kernel<<<dim3(I_ / 32, B_ / 32), dim3(32, 8)>>>(x,  xt,  B_, I_);

    encode_topk_kernel<<<B_ / BM, NTHR, SM_TOT>>>(be, sparse);
    decode_kernel<<<B_, 128>>>(bd, recon);
}